// round 1
// baseline (speedup 1.0000x reference)
#include <cuda_runtime.h>

// EfConv: out[n, k*64+o] = sum_{e: dst_e=n} ef[e,k] * (node_feat[src_e] . W[o]) + b[o]
// Strategy: y = X @ W^T first (8x smaller GEMM), CSR-by-dst build per launch,
// warp-per-node segmented reduction (no atomics in hot loop).

#define MAXN 50000
#define MAXE 800000
#define NF 64
#define ED 8

// Scratch (static __device__ arrays; no allocation anywhere)
__device__ int   g_deg[MAXN];
__device__ int   g_off[MAXN + 1];
__device__ int   g_cur[MAXN];
__device__ int   g_srcP[MAXE];
__device__ float g_efP[(size_t)MAXE * ED];   // 25.6 MB, edge rows permuted by dst
__device__ float g_y[(size_t)MAXN * NF];     // 12.8 MB, L2-resident in main pass

// ---------------- CSR build ----------------

__global__ void k_zero_deg(int N) {
    int i = blockIdx.x * blockDim.x + threadIdx.x;
    if (i < N) g_deg[i] = 0;
}

__global__ void k_hist(const int* __restrict__ dst, int E) {
    int e = blockIdx.x * blockDim.x + threadIdx.x;
    if (e < E) atomicAdd(&g_deg[dst[e]], 1);
}

// Single-block exclusive scan of g_deg -> g_off (and cursor copy).
__global__ void k_scan(int N) {
    __shared__ int sh[1024];
    int t = threadIdx.x;
    int chunk = (N + 1023) / 1024;
    int beg = t * chunk;
    int end = min(beg + chunk, N);
    int s = 0;
    for (int i = beg; i < end; i++) s += g_deg[i];
    sh[t] = s;
    __syncthreads();
    // Hillis-Steele inclusive scan over 1024 partials
    for (int d = 1; d < 1024; d <<= 1) {
        int v = (t >= d) ? sh[t - d] : 0;
        __syncthreads();
        sh[t] += v;
        __syncthreads();
    }
    int run = (t == 0) ? 0 : sh[t - 1];
    for (int i = beg; i < end; i++) {
        g_off[i] = run;
        g_cur[i] = run;
        run += g_deg[i];
    }
    if (t == 1023) g_off[N] = run;   // == E (trailing empty ranges keep run = total)
}

// Scatter edges into dst-grouped order; also permute src ids and ef rows so the
// main pass streams contiguously.
__global__ void k_scatter(const int* __restrict__ src, const int* __restrict__ dst,
                          const float* __restrict__ ef, int E) {
    int e = blockIdx.x * blockDim.x + threadIdx.x;
    if (e >= E) return;
    int pos = atomicAdd(&g_cur[dst[e]], 1);
    g_srcP[pos] = src[e];
    const float4* s4 = (const float4*)(ef + (size_t)e * ED);   // 32B-aligned row
    float4 a = s4[0], c = s4[1];
    float4* o4 = (float4*)(g_efP + (size_t)pos * ED);
    o4[0] = a;
    o4[1] = c;
}

// ---------------- y = X @ W^T ----------------
// 16 nodes per 256-thread block. Thread (o = t&63) handles 4 nodes.
// W row-major in smem with 68-float row pitch: float4-aligned, conflict-free LDS.128.
__global__ void k_ygemm(const float* __restrict__ X, const float* __restrict__ W, int N) {
    __shared__ float Ws[64][68];
    __shared__ float xs[16][64];
    int t = threadIdx.x;
    int base = blockIdx.x * 16;

    for (int idx = t; idx < 64 * 64; idx += 256)
        Ws[idx >> 6][idx & 63] = W[idx];
    for (int idx = t; idx < 16 * 64; idx += 256) {
        int ln = idx >> 6, i = idx & 63;
        int n = base + ln;
        xs[ln][i] = (n < N) ? X[(size_t)n * NF + i] : 0.f;
    }
    __syncthreads();

    int o = t & 63;
    int g = t >> 6;            // 0..3 -> node group g*4 .. g*4+3
    float acc[4] = {0.f, 0.f, 0.f, 0.f};
    #pragma unroll
    for (int i = 0; i < 64; i += 4) {
        float4 wv = *(const float4*)&Ws[o][i];
        #pragma unroll
        for (int r = 0; r < 4; r++) {
            float4 xv = *(const float4*)&xs[g * 4 + r][i];
            acc[r] += wv.x * xv.x + wv.y * xv.y + wv.z * xv.z + wv.w * xv.w;
        }
    }
    #pragma unroll
    for (int r = 0; r < 4; r++) {
        int n = base + g * 4 + r;
        if (n < N) g_y[(size_t)n * NF + o] = acc[r];
    }
}

// ---------------- main: warp-per-node segmented reduction ----------------
// Lane holds o = {lane*2, lane*2+1} across all 8 k => 16 accumulators.
// Per edge: broadcast src + ef row (LDG.128 x2), coalesced 256B y-row read, 16 FFMA/lane.
__global__ void k_main(const float* __restrict__ bvec, float* __restrict__ out, int N) {
    int w = (blockIdx.x * blockDim.x + threadIdx.x) >> 5;
    if (w >= N) return;
    int lane = threadIdx.x & 31;
    int beg = g_off[w], end = g_off[w + 1];

    float acc[16];
    #pragma unroll
    for (int a = 0; a < 16; a++) acc[a] = 0.f;

    for (int j = beg; j < end; j++) {
        int s = g_srcP[j];                                   // uniform -> broadcast
        const float4* e4 = (const float4*)(g_efP + (size_t)j * ED);
        float4 ea = e4[0], eb = e4[1];                       // uniform -> broadcast
        float2 yv = *(const float2*)(g_y + (size_t)s * NF + lane * 2);  // coalesced 256B
        acc[0]  += ea.x * yv.x;  acc[1]  += ea.x * yv.y;
        acc[2]  += ea.y * yv.x;  acc[3]  += ea.y * yv.y;
        acc[4]  += ea.z * yv.x;  acc[5]  += ea.z * yv.y;
        acc[6]  += ea.w * yv.x;  acc[7]  += ea.w * yv.y;
        acc[8]  += eb.x * yv.x;  acc[9]  += eb.x * yv.y;
        acc[10] += eb.y * yv.x;  acc[11] += eb.y * yv.y;
        acc[12] += eb.z * yv.x;  acc[13] += eb.z * yv.y;
        acc[14] += eb.w * yv.x;  acc[15] += eb.w * yv.y;
    }

    float2 bb = *(const float2*)(bvec + lane * 2);
    float* op = out + (size_t)w * (ED * NF);
    #pragma unroll
    for (int k = 0; k < ED; k++) {
        float2 v;
        v.x = acc[2 * k]     + bb.x;
        v.y = acc[2 * k + 1] + bb.y;
        *(float2*)(op + k * NF + lane * 2) = v;   // coalesced 256B per k
    }
}

// ---------------- launch ----------------

extern "C" void kernel_launch(void* const* d_in, const int* in_sizes, int n_in,
                              void* d_out, int out_size) {
    const float* node_feat = (const float*)d_in[0];
    const float* edge_feat = (const float*)d_in[1];
    const float* W         = (const float*)d_in[2];
    const float* b         = (const float*)d_in[3];
    const int*   src       = (const int*)d_in[4];
    const int*   dst       = (const int*)d_in[5];

    int N = in_sizes[0] / NF;     // 50000
    int E = in_sizes[4];          // 800000

    k_zero_deg<<<(N + 255) / 256, 256>>>(N);
    k_hist   <<<(E + 255) / 256, 256>>>(dst, E);
    k_scan   <<<1, 1024>>>(N);
    k_scatter<<<(E + 255) / 256, 256>>>(src, dst, edge_feat, E);
    k_ygemm  <<<(N + 15) / 16, 256>>>(node_feat, W, N);
    k_main   <<<(N * 32 + 255) / 256, 256>>>(b, (float*)d_out, N);
}